// round 15
// baseline (speedup 1.0000x reference)
#include <cuda_runtime.h>
#include <cuda_bf16.h>
#include <math.h>
#include <stdint.h>

// ---------------- static config ----------------
#define B_     8
#define C_     192
#define H_     128
#define W_     128
#define WS_    8
#define SHIFT_ 4
#define HEADS_ 4
#define HD_    48
#define L_     64
#define NW_    256
#define T_     (B_*NW_*L_)         // 131072 tokens
#define HID_   768

// ---------------- scratch (static device globals, ~703 MB) -------------------
__device__ float g_xw [(size_t)T_ * C_];      // shortcut (fp32)
__device__ float g_x1 [(size_t)T_ * C_];      // residual-1 (fp32)
__device__ float g_x2 [(size_t)T_ * C_];      // x2 before scatter (fp32)
__device__ __nv_bfloat16 g_qkv[(size_t)T_ * 576];   // bf16 qkv
__device__ __nv_bfloat16 g_a0 [(size_t)T_ * C_];    // bf16 activations (LN1/attnout/LN2)
__device__ __nv_bfloat16 g_hid[(size_t)T_ * HID_];  // bf16 mlp hidden
// bf16 transposed weights [N][K]
__device__ __nv_bfloat16 g_wqkv[576 * 192];
__device__ __nv_bfloat16 g_wproj[192 * 192];
__device__ __nv_bfloat16 g_w1[768 * 192];
__device__ __nv_bfloat16 g_w2[192 * 768];

enum FBuf { FB_XW = 0, FB_X1 = 1, FB_X2 = 2 };
enum ABuf { AB_A0 = 0, AB_HID = 1, AB_QKV = 2 };
enum WBuf { WB_QKV = 0, WB_PROJ = 1, WB_W1 = 2, WB_W2 = 3 };

__device__ __forceinline__ float* fbuf_ptr(int sel) {
    switch (sel) {
        case FB_XW: return g_xw;
        case FB_X1: return g_x1;
        default:    return g_x2;
    }
}
__device__ __forceinline__ __nv_bfloat16* abuf_ptr(int sel) {
    switch (sel) {
        case AB_A0:  return g_a0;
        case AB_HID: return g_hid;
        default:     return g_qkv;
    }
}
__device__ __forceinline__ __nv_bfloat16* wbuf_ptr(int sel) {
    switch (sel) {
        case WB_QKV:  return g_wqkv;
        case WB_PROJ: return g_wproj;
        case WB_W1:   return g_w1;
        default:      return g_w2;
    }
}

__device__ __forceinline__ void mma_bf16(float c[4],
                                         const uint32_t a[4], const uint32_t b[2]) {
    asm volatile(
        "mma.sync.aligned.m16n8k16.row.col.f32.bf16.bf16.f32 "
        "{%0,%1,%2,%3}, {%4,%5,%6,%7}, {%8,%9}, {%0,%1,%2,%3};"
        : "+f"(c[0]), "+f"(c[1]), "+f"(c[2]), "+f"(c[3])
        : "r"(a[0]), "r"(a[1]), "r"(a[2]), "r"(a[3]), "r"(b[0]), "r"(b[1]));
}

__device__ __forceinline__ void cp_async16(void* smem, const void* gmem) {
    uint32_t s = (uint32_t)__cvta_generic_to_shared(smem);
    asm volatile("cp.async.ca.shared.global [%0], [%1], 16;" :: "r"(s), "l"(gmem));
}

__device__ __forceinline__ uint32_t pack_bf16x2(float lo, float hi) {
    __nv_bfloat162 h = __floats2bfloat162_rn(lo, hi);
    return *(uint32_t*)&h;
}

// ---------------- weight convert + transpose: fp32[K][N] -> bf16[N][K] ------
__global__ __launch_bounds__(256) void convert_w_kernel(int selW, const float* __restrict__ src,
                                                        int K, int N) {
    __nv_bfloat16* dst = wbuf_ptr(selW);
    int i = blockIdx.x * 256 + threadIdx.x;
    if (i < K * N) {
        int n = i / K, k = i - n * K;
        dst[i] = __float2bfloat16(src[(long)k * N + n]);
    }
}

// ---------------- fused gather + LN1: x -> g_xw (fp32) + g_a0 (bf16) --------
#define S2_STR 196
__global__ __launch_bounds__(256) void gather_ln_kernel(const float* __restrict__ x,
                                                        const float* __restrict__ gam,
                                                        const float* __restrict__ bet) {
    __shared__ float s2[32 * S2_STR];
    __shared__ float sg[192], sb[192];
    __shared__ float smu[32], srs[32];
    int blk = blockIdx.x;
    int half = blk & 1;
    int bn = blk >> 1;
    int b = bn / NW_;
    int n = bn % NW_;
    int wh = n >> 4, ww = n & 15;
    long tokbase = (long)bn * 64 + half * 32;
    int tid = threadIdx.x;

    for (int t = tid; t < 192; t += 256) { sg[t] = gam[t]; sb[t] = bet[t]; }

    #pragma unroll
    for (int ci = 0; ci < 4; ci++) {
        #pragma unroll
        for (int t = 0; t < 6; t++) {
            int idx = tid + t * 256;
            int c = idx >> 5, l = idx & 31;
            int hr = (wh * 8 + half * 4 + (l >> 3) + SHIFT_) & 127;
            int wc = (ww * 8 + (l & 7) + SHIFT_) & 127;
            s2[l * S2_STR + ci * 48 + c] = x[(((b * C_ + ci * 48 + c) * H_ + hr) << 7) + wc];
        }
    }
    __syncthreads();

    int l = tid >> 3, part = tid & 7;
    float sum = 0.f;
    #pragma unroll
    for (int u = 0; u < 24; u++) sum += s2[l * S2_STR + part + 8 * u];
    sum += __shfl_xor_sync(0xffffffffu, sum, 1);
    sum += __shfl_xor_sync(0xffffffffu, sum, 2);
    sum += __shfl_xor_sync(0xffffffffu, sum, 4);
    float mu = sum * (1.0f / 192.0f);
    float sq = 0.f;
    #pragma unroll
    for (int u = 0; u < 24; u++) {
        float d = s2[l * S2_STR + part + 8 * u] - mu;
        sq += d * d;
    }
    sq += __shfl_xor_sync(0xffffffffu, sq, 1);
    sq += __shfl_xor_sync(0xffffffffu, sq, 2);
    sq += __shfl_xor_sync(0xffffffffu, sq, 4);
    float rstd = rsqrtf(sq * (1.0f / 192.0f) + 1e-5f);
    if (part == 0) { smu[l] = mu; srs[l] = rstd; }
    __syncthreads();

    for (int idx = tid; idx < 32 * 192; idx += 256) {
        int l2 = idx / 192, c = idx - l2 * 192;
        float v = s2[l2 * S2_STR + c];
        long off = (tokbase + l2) * C_ + c;
        g_xw[off] = v;
        g_a0[off] = __float2bfloat16((v - smu[l2]) * srs[l2] * sg[c] + sb[c]);
    }
}

// ---------------- LN2: g_x1 (fp32) -> g_a0 (bf16) ---------------------------
__global__ __launch_bounds__(256) void ln2_kernel(const float* __restrict__ gam,
                                                  const float* __restrict__ bet) {
    int warp = threadIdx.x >> 5;
    int lane = threadIdx.x & 31;
    long tok = (long)blockIdx.x * 8 + warp;
    const float* row = g_x1 + tok * C_;
    float v[6];
    float sum = 0.f;
    #pragma unroll
    for (int u = 0; u < 6; u++) { v[u] = row[lane + 32 * u]; sum += v[u]; }
    #pragma unroll
    for (int o = 16; o; o >>= 1) sum += __shfl_xor_sync(0xffffffffu, sum, o);
    float mu = sum * (1.0f / 192.0f);
    float sq = 0.f;
    #pragma unroll
    for (int u = 0; u < 6; u++) { float d = v[u] - mu; sq += d * d; }
    #pragma unroll
    for (int o = 16; o; o >>= 1) sq += __shfl_xor_sync(0xffffffffu, sq, o);
    float rstd = rsqrtf(sq * (1.0f / 192.0f) + 1e-5f);
    __nv_bfloat16* orow = g_a0 + tok * C_;
    #pragma unroll
    for (int u = 0; u < 6; u++) {
        int c = lane + 32 * u;
        orow[c] = __float2bfloat16((v[u] - mu) * rstd * gam[c] + bet[c]);
    }
}

// ---------------- scatter: g_x2 -> out (reverse window + roll) --------------
__global__ __launch_bounds__(256) void scatter_kernel(float* __restrict__ out) {
    __shared__ float s[48 * 65];
    int blk = blockIdx.x;
    int b = blk / NW_;
    int n = blk % NW_;
    int wh = n >> 4, ww = n & 15;
    long tokbase = (long)blk * L_;
    int tid = threadIdx.x;
    for (int ci = 0; ci < 4; ci++) {
        #pragma unroll
        for (int t = 0; t < 12; t++) {
            int idx = tid + t * 256;
            int l = idx / 48, c = idx % 48;
            s[c * 65 + l] = g_x2[(tokbase + l) * C_ + ci * 48 + c];
        }
        __syncthreads();
        #pragma unroll
        for (int t = 0; t < 12; t++) {
            int idx = tid + t * 256;
            int c = idx >> 6, l = idx & 63;
            int hr = (wh * 8 + (l >> 3) + SHIFT_) & 127;
            int wc = (ww * 8 + (l & 7) + SHIFT_) & 127;
            out[(((b * C_ + ci * 48 + c) * H_ + hr) << 7) + wc] = s[c * 65 + l];
        }
        __syncthreads();
    }
}

// ---------------- bf16 tensor-core GEMM -------------------------------------
// 128x96 tile, 8 warps, warp 32x48, k-chunk 16, cp.async double-buffer.
// OP_BIAS / OP_BIAS_GELU write bf16 (abuf); OP_BIAS_RES writes fp32 + residual.
enum { OP_BIAS = 0, OP_BIAS_RES = 1, OP_BIAS_GELU = 2 };

template<int OP, int K>
__global__ __launch_bounds__(256) void tgemm_bf16(int selA, int selR, int selO,
                                                  int selW,
                                                  const float* __restrict__ bias,
                                                  int M, int N) {
    const __nv_bfloat16* A = abuf_ptr(selA);
    const __nv_bfloat16* Wt = wbuf_ptr(selW);
    const float* R = fbuf_ptr(selR);

    __shared__ uint32_t As[2][128][12];
    __shared__ uint32_t Bs[2][96][12];

    int tid = threadIdx.x;
    int warp = tid >> 5;
    int lane = tid & 31;
    int gid = lane >> 2;
    int tig = lane & 3;
    int wm = (warp >> 1) * 32;
    int wn = (warp & 1) * 48;
    int m0 = blockIdx.y * 128;
    int n0 = blockIdx.x * 96;

    int a_row = tid >> 1, a_h = tid & 1;
    int b_row = tid >> 1, b_h = tid & 1;

    float acc[2][6][4];
    #pragma unroll
    for (int i = 0; i < 2; i++)
        #pragma unroll
        for (int j = 0; j < 6; j++)
            #pragma unroll
            for (int c = 0; c < 4; c++) acc[i][j][c] = 0.f;

    const int NKC = K >> 4;

    cp_async16((char*)&As[0][a_row][0] + a_h * 16, A + (long)(m0 + a_row) * K + a_h * 8);
    if (tid < 192)
        cp_async16((char*)&Bs[0][b_row][0] + b_h * 16, Wt + (long)(n0 + b_row) * K + b_h * 8);
    asm volatile("cp.async.commit_group;");

    int bf = 0;
    for (int it = 0; it < NKC; it++) {
        asm volatile("cp.async.wait_group 0;");
        __syncthreads();
        if (it + 1 < NKC) {
            int kk = (it + 1) << 4;
            int nb = bf ^ 1;
            cp_async16((char*)&As[nb][a_row][0] + a_h * 16,
                       A + (long)(m0 + a_row) * K + kk + a_h * 8);
            if (tid < 192)
                cp_async16((char*)&Bs[nb][b_row][0] + b_h * 16,
                           Wt + (long)(n0 + b_row) * K + kk + b_h * 8);
            asm volatile("cp.async.commit_group;");
        }

        uint32_t a[2][4], b[6][2];
        #pragma unroll
        for (int mi = 0; mi < 2; mi++) {
            int mrow = wm + mi * 16 + gid;
            a[mi][0] = As[bf][mrow][tig];
            a[mi][1] = As[bf][mrow + 8][tig];
            a[mi][2] = As[bf][mrow][tig + 4];
            a[mi][3] = As[bf][mrow + 8][tig + 4];
        }
        #pragma unroll
        for (int ni = 0; ni < 6; ni++) {
            int ncol = wn + ni * 8 + gid;
            b[ni][0] = Bs[bf][ncol][tig];
            b[ni][1] = Bs[bf][ncol][tig + 4];
        }
        #pragma unroll
        for (int mi = 0; mi < 2; mi++)
            #pragma unroll
            for (int ni = 0; ni < 6; ni++)
                mma_bf16(acc[mi][ni], a[mi], b[ni]);

        bf ^= 1;
    }

    #pragma unroll
    for (int mi = 0; mi < 2; mi++) {
        #pragma unroll
        for (int ni = 0; ni < 6; ni++) {
            int col = n0 + wn + ni * 8 + tig * 2;
            float bv0 = bias[col], bv1 = bias[col + 1];
            #pragma unroll
            for (int h = 0; h < 2; h++) {
                long row = m0 + wm + mi * 16 + gid + h * 8;
                float v0 = acc[mi][ni][h * 2 + 0] + bv0;
                float v1 = acc[mi][ni][h * 2 + 1] + bv1;
                if (OP == OP_BIAS_GELU) {
                    v0 = 0.5f * v0 * (1.0f + erff(v0 * 0.70710678118654752f));
                    v1 = 0.5f * v1 * (1.0f + erff(v1 * 0.70710678118654752f));
                }
                if (OP == OP_BIAS || OP == OP_BIAS_GELU) {
                    __nv_bfloat16* Oh = abuf_ptr(selO);
                    __nv_bfloat162 p;
                    p.x = __float2bfloat16(v0);
                    p.y = __float2bfloat16(v1);
                    *(__nv_bfloat162*)(Oh + row * N + col) = p;
                } else {
                    v0 += R[row * N + col];
                    v1 += R[row * N + col + 1];
                    float* Of = fbuf_ptr(selO);
                    *(float2*)(Of + row * N + col) = make_float2(v0, v1);
                }
            }
        }
    }
}

// ---------------- bf16 tensor-core windowed attention -----------------------
// one 128-thread block per (b, window, head); 4 warps, 16 rows each.
// Q/K rows [l][d] bf16, u32 stride 28 (28*gid+tig permutes mod 32).
// V d-major [d][l] stride 36; P [r][j] stride 36 (4*gid+tig permutes).
#define QS 28
#define VS 36
#define PS 36

__global__ __launch_bounds__(128) void attn_bf16_kernel(const float* __restrict__ bias_table) {
    __shared__ uint32_t sQK[2 * 64 * QS];   // Q at 0, K at 1792; P aliases Q (needs 64*36=2304 <= 3584)
    __shared__ uint32_t sV[48 * VS];
    __shared__ float bb[225];

    uint32_t* sQ = sQK;
    uint32_t* sK = sQK + 64 * QS;
    uint32_t* sP = sQK;

    int blk = blockIdx.x;
    int head = blk & 3;
    int bn = blk >> 2;
    int n = bn % NW_;
    int wh = n >> 4, ww = n & 15;
    long tokbase = (long)bn * 64;
    int tid = threadIdx.x;
    int warp = tid >> 5;
    int lane = tid & 31;
    int gid = lane >> 2;
    int tig = lane & 3;

    for (int t = tid; t < 225; t += 128) bb[t] = bias_table[head * 225 + t];

    // load Q,K rows (raw u32 copies); V transposed to d-major
    uint16_t* sv16 = (uint16_t*)sV;
    for (int t = tid; t < 384; t += 128) {     // 64 rows x 6 uint4
        int l = t / 6, q4 = t % 6;
        const __nv_bfloat16* base = g_qkv + (tokbase + l) * 576 + head * 48 + q4 * 8;
        uint4 q = *(const uint4*)(base);
        uint4 k = *(const uint4*)(base + 192);
        uint4 v = *(const uint4*)(base + 384);
        *(uint4*)&sQ[l * QS + q4 * 4] = q;
        *(uint4*)&sK[l * QS + q4 * 4] = k;
        uint16_t* v16 = (uint16_t*)&v;
        #pragma unroll
        for (int j = 0; j < 8; j++)
            sv16[(q4 * 8 + j) * (VS * 2) + l] = v16[j];
    }
    __syncthreads();

    // scores: S = Q K^T (raw), 3 bf16 k-chunks over d=48
    int r0 = warp * 16 + gid, r1 = r0 + 8;
    float acc[8][4];
    #pragma unroll
    for (int ni = 0; ni < 8; ni++)
        #pragma unroll
        for (int c = 0; c < 4; c++) acc[ni][c] = 0.f;

    #pragma unroll
    for (int kc = 0; kc < 3; kc++) {
        uint32_t a[4];
        a[0] = sQ[r0 * QS + kc * 8 + tig];
        a[1] = sQ[r1 * QS + kc * 8 + tig];
        a[2] = sQ[r0 * QS + kc * 8 + tig + 4];
        a[3] = sQ[r1 * QS + kc * 8 + tig + 4];
        #pragma unroll
        for (int ni = 0; ni < 8; ni++) {
            uint32_t b[2];
            b[0] = sK[(ni * 8 + gid) * QS + kc * 8 + tig];
            b[1] = sK[(ni * 8 + gid) * QS + kc * 8 + tig + 4];
            mma_bf16(acc[ni], a, b);
        }
    }

    // scale + bias + shift mask + softmax
    const float scale = 0.14433756729740643f;   // 1/sqrt(48)
    int ih0 = r0 >> 3, iw0 = r0 & 7;
    int ih1 = r1 >> 3, iw1 = r1 & 7;
    int reg_i0 = ((wh == 15) ? (ih0 < 4 ? 3 : 6) : 0) + ((ww == 15) ? (iw0 < 4 ? 1 : 2) : 0);
    int reg_i1 = ((wh == 15) ? (ih1 < 4 ? 3 : 6) : 0) + ((ww == 15) ? (iw1 < 4 ? 1 : 2) : 0);

    float mx0 = -1e30f, mx1 = -1e30f;
    #pragma unroll
    for (int ni = 0; ni < 8; ni++) {
        #pragma unroll
        for (int hh = 0; hh < 2; hh++) {
            int j = ni * 8 + tig * 2 + hh;
            int jh = j >> 3, jw = j & 7;
            int reg_j = ((wh == 15) ? (jh < 4 ? 3 : 6) : 0) + ((ww == 15) ? (jw < 4 ? 1 : 2) : 0);
            float bt0 = (reg_i0 != reg_j) ? -100.0f : bb[(ih0 - jh + 7) * 15 + (iw0 - jw + 7)];
            float bt1 = (reg_i1 != reg_j) ? -100.0f : bb[(ih1 - jh + 7) * 15 + (iw1 - jw + 7)];
            acc[ni][hh]     = acc[ni][hh] * scale + bt0;
            acc[ni][2 + hh] = acc[ni][2 + hh] * scale + bt1;
            mx0 = fmaxf(mx0, acc[ni][hh]);
            mx1 = fmaxf(mx1, acc[ni][2 + hh]);
        }
    }
    mx0 = fmaxf(mx0, __shfl_xor_sync(0xffffffffu, mx0, 1));
    mx0 = fmaxf(mx0, __shfl_xor_sync(0xffffffffu, mx0, 2));
    mx1 = fmaxf(mx1, __shfl_xor_sync(0xffffffffu, mx1, 1));
    mx1 = fmaxf(mx1, __shfl_xor_sync(0xffffffffu, mx1, 2));
    float s0 = 0.f, s1 = 0.f;
    #pragma unroll
    for (int ni = 0; ni < 8; ni++) {
        #pragma unroll
        for (int hh = 0; hh < 2; hh++) {
            acc[ni][hh]     = __expf(acc[ni][hh] - mx0);     s0 += acc[ni][hh];
            acc[ni][2 + hh] = __expf(acc[ni][2 + hh] - mx1); s1 += acc[ni][2 + hh];
        }
    }
    s0 += __shfl_xor_sync(0xffffffffu, s0, 1);
    s0 += __shfl_xor_sync(0xffffffffu, s0, 2);
    s1 += __shfl_xor_sync(0xffffffffu, s1, 1);
    s1 += __shfl_xor_sync(0xffffffffu, s1, 2);
    float inv0 = 1.0f / s0, inv1 = 1.0f / s1;

    __syncthreads();   // all warps done with sQ/sK before P overwrites

    #pragma unroll
    for (int ni = 0; ni < 8; ni++) {
        sP[r0 * PS + ni * 4 + tig] = pack_bf16x2(acc[ni][0] * inv0, acc[ni][1] * inv0);
        sP[r1 * PS + ni * 4 + tig] = pack_bf16x2(acc[ni][2] * inv1, acc[ni][3] * inv1);
    }
    __syncthreads();

    // O = P V : 4 bf16 k-chunks over l=64
    float oacc[6][4];
    #pragma unroll
    for (int ni = 0; ni < 6; ni++)
        #pragma unroll
        for (int c = 0; c < 4; c++) oacc[ni][c] = 0.f;

    #pragma unroll
    for (int kt = 0; kt < 4; kt++) {
        uint32_t a[4];
        a[0] = sP[r0 * PS + kt * 8 + tig];
        a[1] = sP[r1 * PS + kt * 8 + tig];
        a[2] = sP[r0 * PS + kt * 8 + tig + 4];
        a[3] = sP[r1 * PS + kt * 8 + tig + 4];
        #pragma unroll
        for (int ni = 0; ni < 6; ni++) {
            uint32_t b[2];
            b[0] = sV[(ni * 8 + gid) * VS + kt * 8 + tig];
            b[1] = sV[(ni * 8 + gid) * VS + kt * 8 + tig + 4];
            mma_bf16(oacc[ni], a, b);
        }
    }

    #pragma unroll
    for (int ni = 0; ni < 6; ni++) {
        int col = ni * 8 + tig * 2;
        __nv_bfloat16* p0 = g_a0 + (tokbase + r0) * C_ + head * 48 + col;
        __nv_bfloat16* p1 = g_a0 + (tokbase + r1) * C_ + head * 48 + col;
        __nv_bfloat162 o0, o1;
        o0.x = __float2bfloat16(oacc[ni][0]); o0.y = __float2bfloat16(oacc[ni][1]);
        o1.x = __float2bfloat16(oacc[ni][2]); o1.y = __float2bfloat16(oacc[ni][3]);
        *(__nv_bfloat162*)p0 = o0;
        *(__nv_bfloat162*)p1 = o1;
    }
}

// ---------------- launcher ---------------------------------------------------
extern "C" void kernel_launch(void* const* d_in, const int* in_sizes, int n_in,
                              void* d_out, int out_size) {
    const float* x   = (const float*)d_in[0];
    const float* bt  = (const float*)d_in[1];
    const float* qw  = (const float*)d_in[2];
    const float* qb  = (const float*)d_in[3];
    const float* pw  = (const float*)d_in[4];
    const float* pb  = (const float*)d_in[5];
    const float* g1  = (const float*)d_in[6];
    const float* b1  = (const float*)d_in[7];
    const float* g2  = (const float*)d_in[8];
    const float* b2  = (const float*)d_in[9];
    const float* w1  = (const float*)d_in[10];
    const float* bb1 = (const float*)d_in[11];
    const float* w2  = (const float*)d_in[12];
    const float* bb2 = (const float*)d_in[13];
    float* out = (float*)d_out;

    // 0. convert + transpose weights to bf16 [N][K]
    convert_w_kernel<<<(192 * 576 + 255) / 256, 256>>>(WB_QKV, qw, 192, 576);
    convert_w_kernel<<<(192 * 192 + 255) / 256, 256>>>(WB_PROJ, pw, 192, 192);
    convert_w_kernel<<<(192 * 768 + 255) / 256, 256>>>(WB_W1, w1, 192, 768);
    convert_w_kernel<<<(768 * 192 + 255) / 256, 256>>>(WB_W2, w2, 768, 192);

    // 1. gather + LN1  (x -> g_xw fp32, g_a0 bf16)
    gather_ln_kernel<<<B_ * NW_ * 2, 256>>>(x, g1, b1);
    // 2. QKV GEMM: bf16 out -> g_qkv
    tgemm_bf16<OP_BIAS, 192><<<dim3(576 / 96, T_ / 128), 256>>>(AB_A0, 0, AB_QKV, WB_QKV, qb, T_, 576);
    // 3. bf16 attention (g_qkv -> g_a0)
    attn_bf16_kernel<<<B_ * NW_ * HEADS_, 128>>>(bt);
    // 4. proj + residual: g_a0 @ pw + g_xw -> g_x1 fp32
    tgemm_bf16<OP_BIAS_RES, 192><<<dim3(192 / 96, T_ / 128), 256>>>(AB_A0, FB_XW, FB_X1, WB_PROJ, pb, T_, 192);
    // 5. LN2 (g_x1 -> g_a0 bf16)
    ln2_kernel<<<T_ / 8, 256>>>(g2, b2);
    // 6. MLP1 + GELU: g_a0 @ w1 -> g_hid bf16
    tgemm_bf16<OP_BIAS_GELU, 192><<<dim3(768 / 96, T_ / 128), 256>>>(AB_A0, 0, AB_HID, WB_W1, bb1, T_, 768);
    // 7. MLP2 + residual: g_hid @ w2 + g_x1 -> g_x2 fp32
    tgemm_bf16<OP_BIAS_RES, 768><<<dim3(192 / 96, T_ / 128), 256>>>(AB_HID, FB_X1, FB_X2, WB_W2, bb2, T_, 192);
    // 8. scatter (g_x2 -> out)
    scatter_kernel<<<B_ * NW_, 256>>>(out);
}